// round 12
// baseline (speedup 1.0000x reference)
#include <cuda_runtime.h>
#include <cuda_bf16.h>

// Leapfrog integrator, GM = 1, A_SCALE = 1.
// One thread handles TWO particles (i and i+n/2), each as a packed f32x2
// pair (trail = lane lo, lead = lane hi): 4 trajectories per thread,
// 2 independent dependency chains for ILP, f32x2 FFMA2 math throughout
// (halves fma-pipe rt cost vs scalar FFMA).
//
// Force: 1/(r(1+r)^2+eps) = u*g^2 per lane; u = rsqrt(s) fresh each step
// (the only MUFU); g = 1/(1+r) Newton-tracked (2 iterations, proven
// rel_err 2.35e-5). Signs: nu = -u, nh = fma2(s,nu,-1) = -(1+r),
// cu = (+c)*nu = -c*u; kick = p = fma2(cu*g*g, q, p).

typedef unsigned long long f2;   // packed f32x2 (lo, hi)

__device__ __forceinline__ f2 pack2(float lo, float hi) {
    f2 r; asm("mov.b64 %0, {%1, %2};" : "=l"(r) : "f"(lo), "f"(hi)); return r;
}
__device__ __forceinline__ void unpack2(f2 v, float& lo, float& hi) {
    asm("mov.b64 {%0, %1}, %2;" : "=f"(lo), "=f"(hi) : "l"(v));
}
__device__ __forceinline__ f2 fma2(f2 a, f2 b, f2 c) {
    f2 r; asm("fma.rn.f32x2 %0, %1, %2, %3;" : "=l"(r) : "l"(a), "l"(b), "l"(c)); return r;
}
__device__ __forceinline__ f2 mul2(f2 a, f2 b) {
    f2 r; asm("mul.rn.f32x2 %0, %1, %2;" : "=l"(r) : "l"(a), "l"(b)); return r;
}
__device__ __forceinline__ float rsqrt_approx(float x) {
    float y; asm("rsqrt.approx.f32 %0, %1;" : "=f"(y) : "f"(x)); return y;
}
__device__ __forceinline__ float rcp_approx(float x) {
    float y; asm("rcp.approx.f32 %0, %1;" : "=f"(y) : "f"(x)); return y;
}

struct StateP {                  // one particle: trail/lead packed per lane
    f2 qx, qy, qz, px, py, pz;
    f2 g;                        // tracked 1/(1+r) per lane
    f2 dt2;                      // +dt both lanes
    f2 hdt2;                     // +dt/2 both lanes
};

__device__ __forceinline__ f2 EPS30() { return pack2(1e-30f, 1e-30f); }

__device__ __forceinline__ void kick2(StateP& t, f2 cf) {
    t.px = fma2(cf, t.qx, t.px);
    t.py = fma2(cf, t.qy, t.py);
    t.pz = fma2(cf, t.qz, t.pz);
}
__device__ __forceinline__ void drift2(StateP& t) {
    t.qx = fma2(t.dt2, t.px, t.qx);
    t.qy = fma2(t.dt2, t.py, t.qy);
    t.qz = fma2(t.dt2, t.pz, t.qz);
}

// Force eval + kick; cpos = +dt (interior) or +dt/2 (half kick).
__device__ __forceinline__ void force_kick2(StateP& t, f2 cpos,
                                            f2 eps30, f2 m1, f2 two2) {
    f2 s = fma2(t.qx, t.qx, fma2(t.qy, t.qy, fma2(t.qz, t.qz, eps30)));
    float s0, s1; unpack2(s, s0, s1);          // free: register pair
    f2 u  = pack2(rsqrt_approx(s0), rsqrt_approx(s1));   // 2 MUFU + pack
    f2 nu = mul2(u, m1);                       // -u
    f2 nh = fma2(s, nu, m1);                   // -(1 + r),  r = s*u
    f2 cu = mul2(cpos, nu);                    // c*u with c = -cpos
    f2 g  = t.g;                               // seed: previous 1/(1+r)
    g = mul2(g, fma2(nh, g, two2));            // Newton 1: g*(2 - h*g)
    g = mul2(g, fma2(nh, g, two2));            // Newton 2
    t.g = g;
    kick2(t, mul2(cu, mul2(g, g)));            // cf = c*u*g^2
}

// Seed g = 1/(1+r) with MUFU rcp + one Newton polish; opening half kick.
__device__ __forceinline__ void open_half_kick(StateP& t,
                                               f2 eps30, f2 m1, f2 two2) {
    f2 s = fma2(t.qx, t.qx, fma2(t.qy, t.qy, fma2(t.qz, t.qz, eps30)));
    float s0, s1; unpack2(s, s0, s1);
    f2 u  = pack2(rsqrt_approx(s0), rsqrt_approx(s1));
    f2 nu = mul2(u, m1);
    f2 nh = fma2(s, nu, m1);                   // -(1+r)
    float h0, h1; unpack2(nh, h0, h1);
    f2 g = pack2(rcp_approx(-h0), rcp_approx(-h1));
    g = mul2(g, fma2(nh, g, two2));            // polish to ~1 ulp
    t.g = g;
    f2 cu = mul2(t.hdt2, nu);                  // (-dt/2)*u
    kick2(t, mul2(cu, mul2(g, g)));
}

__device__ __forceinline__ void load_pair(StateP& st, const float* __restrict__ w_trail,
                                          const float* __restrict__ w_lead, int i) {
    const float2* str = reinterpret_cast<const float2*>(w_trail + (size_t)i * 6);
    const float2* sld = reinterpret_cast<const float2*>(w_lead  + (size_t)i * 6);
    float2 t0 = str[0], t1 = str[1], t2 = str[2];
    float2 l0 = sld[0], l1 = sld[1], l2 = sld[2];
    st.qx = pack2(t0.x, l0.x);
    st.qy = pack2(t0.y, l0.y);
    st.qz = pack2(t1.x, l1.x);
    st.px = pack2(t1.y, l1.y);
    st.py = pack2(t2.x, l2.x);
    st.pz = pack2(t2.y, l2.y);
}

__device__ __forceinline__ void store_pair(const StateP& st, float* __restrict__ out, int i) {
    float tqx, lqx, tqy, lqy, tqz, lqz, tpx, lpx, tpy, lpy, tpz, lpz;
    unpack2(st.qx, tqx, lqx); unpack2(st.qy, tqy, lqy); unpack2(st.qz, tqz, lqz);
    unpack2(st.px, tpx, lpx); unpack2(st.py, tpy, lpy); unpack2(st.pz, tpz, lpz);
    float4* dst = reinterpret_cast<float4*>(out + (size_t)i * 12);
    dst[0] = make_float4(tqx, tqy, tqz, tpx);
    dst[1] = make_float4(tpy, tpz, lqx, lqy);
    dst[2] = make_float4(lqz, lpx, lpy, lpz);
}

__global__ void __launch_bounds__(32)
stream_integrate_kernel(const float* __restrict__ ts,
                        const float* __restrict__ w_lead,
                        const float* __restrict__ w_trail,
                        const int*   __restrict__ n_steps_p,
                        float* __restrict__ out,
                        int n) {
    int half = n >> 1;
    int i = blockIdx.x * blockDim.x + threadIdx.x;
    if (i >= half) return;
    int j = i + half;

    StateP A, B;
    load_pair(A, w_trail, w_lead, i);
    load_pair(B, w_trail, w_lead, j);

    float t_f = __ldg(ts + (n - 1)) + 0.001f;
    int   nst = *n_steps_p;
    float inv_n = 1.0f / (float)nst;
    float dtA = (t_f - ts[i]) * inv_n;
    float dtB = (t_f - ts[j]) * inv_n;
    A.dt2  = pack2(dtA, dtA);  A.hdt2 = pack2(0.5f * dtA, 0.5f * dtA);
    B.dt2  = pack2(dtB, dtB);  B.hdt2 = pack2(0.5f * dtB, 0.5f * dtB);

    f2 eps30 = EPS30();
    f2 m1    = pack2(-1.0f, -1.0f);
    f2 two2  = pack2(2.0f, 2.0f);

    open_half_kick(A, eps30, m1, two2);
    open_half_kick(B, eps30, m1, two2);

    if (nst == 64) {
        #pragma unroll 3
        for (int k = 0; k < 63; ++k) {
            drift2(A);
            drift2(B);
            force_kick2(A, A.dt2, eps30, m1, two2);
            force_kick2(B, B.dt2, eps30, m1, two2);
        }
    } else {
        for (int k = 0; k < nst - 1; ++k) {
            drift2(A);
            drift2(B);
            force_kick2(A, A.dt2, eps30, m1, two2);
            force_kick2(B, B.dt2, eps30, m1, two2);
        }
    }

    // Closing step: drift + half kick.
    drift2(A);
    drift2(B);
    force_kick2(A, A.hdt2, eps30, m1, two2);
    force_kick2(B, B.hdt2, eps30, m1, two2);

    store_pair(A, out, i);
    store_pair(B, out, j);
}

extern "C" void kernel_launch(void* const* d_in, const int* in_sizes, int n_in,
                              void* d_out, int out_size) {
    const float* ts      = (const float*)d_in[0];
    const float* w_lead  = (const float*)d_in[1];
    const float* w_trail = (const float*)d_in[2];
    const int*   n_steps = (const int*)d_in[3];
    float*       out     = (float*)d_out;

    int n = in_sizes[0];                 // 65536 particles
    int half = n >> 1;                   // 32768 threads, 2 particles each
    int block = 32;
    int grid = (half + block - 1) / block;   // 1024 single-warp CTAs
    stream_integrate_kernel<<<grid, block>>>(ts, w_lead, w_trail, n_steps, out, n);
}

// round 13
// speedup vs baseline: 1.1106x; 1.1106x over previous
#include <cuda_runtime.h>
#include <cuda_bf16.h>

// Leapfrog integrator, GM = 1, A_SCALE = 1. One thread per (particle, stream):
// tid = 2*i + s (s=0 trail, s=1 lead) == output row index -> contiguous stores.
//
// Force scalar 1/(r(1+r)^2 + eps) = u * g^2, u = rsqrt(s) (the only MUFU per
// step). g = 1/(1+r) Newton-tracked across steps (seed = previous g, TWO
// iterations -> measured rel_err 2.35e-5, 40x under tolerance).
// h = 1 + r computed as fma(s, u, 1) (r = s*u folded away).
// Interior kicks fused: one p += dt*a per interior step; kick coefficient
// folded: kick = p = fma(cu*g*g, q, p), cu = c*u computed off the chain.
//
// Launch: block 128 -> 1024 CTAs (halves CTA dispatch ramp vs block 64 while
// keeping max 28 resident warps/SM). Interior loop fully unrolled so ptxas
// can overlap step k's kick with step k+1's dot product.

__device__ __forceinline__ float rsqrt_approx(float x) {
    float y; asm("rsqrt.approx.f32 %0, %1;" : "=f"(y) : "f"(x)); return y;
}
__device__ __forceinline__ float rcp_approx(float x) {
    float y; asm("rcp.approx.f32 %0, %1;" : "=f"(y) : "f"(x)); return y;
}

struct State {
    float qx, qy, qz, px, py, pz;
    float g;                       // tracked 1/(1+r)
};

__device__ __forceinline__ void kick(State& t, float cf) {
    t.px = fmaf(cf, t.qx, t.px);
    t.py = fmaf(cf, t.qy, t.py);
    t.pz = fmaf(cf, t.qz, t.pz);
}
__device__ __forceinline__ void drift(State& t, float dt) {
    t.qx = fmaf(dt, t.px, t.qx);
    t.qy = fmaf(dt, t.py, t.qy);
    t.qz = fmaf(dt, t.pz, t.qz);
}

// Force eval + kick with coefficient c (= -dt or -dt/2). 13 FP + 1 MUFU.
__device__ __forceinline__ void force_kick(State& t, float c) {
    float s  = fmaf(t.qx, t.qx, fmaf(t.qy, t.qy, fmaf(t.qz, t.qz, 1e-30f)));
    float u  = rsqrt_approx(s);             // MUFU
    float cu = c * u;                       // off the critical chain
    float h  = fmaf(s, u, 1.0f);            // 1 + r  (r = s*u), single rounding
    float g  = t.g;                         // seed: previous step's 1/(1+r)
    g = g * fmaf(-h, g, 2.0f);              // Newton 1
    g = g * fmaf(-h, g, 2.0f);              // Newton 2
    t.g = g;
    kick(t, cu * (g * g));                  // cf = c * u * g^2
}

__global__ void __launch_bounds__(128)
stream_integrate_kernel(const float* __restrict__ ts,
                        const float* __restrict__ w_lead,
                        const float* __restrict__ w_trail,
                        const int*   __restrict__ n_steps_p,
                        float* __restrict__ out,
                        int n) {
    int tid = blockIdx.x * blockDim.x + threadIdx.x;
    if (tid >= 2 * n) return;

    int i = tid >> 1;
    int s_ = tid & 1;
    const float* w0 = s_ ? w_lead : w_trail;

    const float2* src = reinterpret_cast<const float2*>(w0 + (size_t)i * 6);
    float2 v0 = src[0];
    float2 v1 = src[1];
    float2 v2 = src[2];

    State st;
    st.qx = v0.x; st.qy = v0.y; st.qz = v1.x;
    st.px = v1.y; st.py = v2.x; st.pz = v2.y;

    float t_f = __ldg(ts + (n - 1)) + 0.001f;
    int   nst = *n_steps_p;
    // Fast reciprocal divide (nst = 64 -> rcp exact; Newton polish for the
    // general case).
    float rn  = rcp_approx((float)nst);
    rn = rn * fmaf(-(float)nst, rn, 2.0f);
    float dt  = (t_f - ts[i]) * rn;
    float ndt  = -dt;
    float nhdt = 0.5f * ndt;

    // Opening half kick: seed g with MUFU rcp + one Newton polish (~1 ulp).
    {
        float s = fmaf(st.qx, st.qx, fmaf(st.qy, st.qy, fmaf(st.qz, st.qz, 1e-30f)));
        float u = rsqrt_approx(s);
        float h = fmaf(s, u, 1.0f);
        float g = rcp_approx(h);
        g = g * fmaf(-h, g, 2.0f);
        st.g = g;
        kick(st, (nhdt * u) * (g * g));
    }

    if (nst == 64) {
        #pragma unroll
        for (int k = 0; k < 63; ++k) {
            drift(st, dt);
            force_kick(st, ndt);
        }
    } else {
        for (int k = 0; k < nst - 1; ++k) {
            drift(st, dt);
            force_kick(st, ndt);
        }
    }

    // Closing step: drift + half kick.
    drift(st, dt);
    force_kick(st, nhdt);

    float2* dst = reinterpret_cast<float2*>(out + (size_t)tid * 6);
    dst[0] = make_float2(st.qx, st.qy);
    dst[1] = make_float2(st.qz, st.px);
    dst[2] = make_float2(st.py, st.pz);
}

extern "C" void kernel_launch(void* const* d_in, const int* in_sizes, int n_in,
                              void* d_out, int out_size) {
    const float* ts      = (const float*)d_in[0];
    const float* w_lead  = (const float*)d_in[1];
    const float* w_trail = (const float*)d_in[2];
    const int*   n_steps = (const int*)d_in[3];
    float*       out     = (float*)d_out;

    int n = in_sizes[0];                 // 65536 particles
    int total = 2 * n;                   // 131072 trajectories
    int block = 128;                     // 1024 CTAs, max 28 warps/SM resident
    int grid = (total + block - 1) / block;
    stream_integrate_kernel<<<grid, block>>>(ts, w_lead, w_trail, n_steps, out, n);
}